// round 2
// baseline (speedup 1.0000x reference)
#include <cuda_runtime.h>
#include <cstddef>

// Shapes (fixed by the problem)
//   query_embed [2,32,64,128] f32   -> 4096 rows
//   doc_embed   [2,32,1024,128] f32 -> 65536 rows
//   r           [1024,128] f32
//   out         [32,2,64,1024] f32
#define L_DIM   2
#define BAT     32
#define A_DIM   64
#define B_DIM   1024
#define D_DIM   128
#define NBITS   1024

#define BM 128
#define BN 128
#define BK 32
#define STR (BK + 1)   // smem row stride (pad 1 -> conflict-free scalar reads)

// Packed sign codes: 32 uint32 words per row (1024 bits)
__device__ unsigned g_codes_q[L_DIM * BAT * A_DIM * (NBITS / 32)];
__device__ unsigned g_codes_d[L_DIM * BAT * B_DIM * (NBITS / 32)];

// ---------------------------------------------------------------------------
// Kernel 1: C = sign(E @ R^T) packed into bits.
// E: [M,128] row-major (k contiguous), R: [1024,128] row-major (k contiguous)
// -> NT GEMM. Tile 128x128, K-chunks of 32, 256 threads, 8x8 microtile with
// strided mapping m = ty + 16*i, n = tx + 16*j.
// ---------------------------------------------------------------------------
__global__ __launch_bounds__(256, 2)
void codes_kernel(const float* __restrict__ emb,
                  const float* __restrict__ rmat,
                  unsigned* __restrict__ codes)
{
    __shared__ float Es[BM][STR];
    __shared__ float Rs[BN][STR];

    const int t  = threadIdx.x;
    const int tx = t & 15;
    const int ty = t >> 4;
    const int bn = blockIdx.x;        // which 128-bit group of NBITS (0..7)
    const int bm = blockIdx.y;        // which 128-row tile of M

    const float* eg = emb  + (size_t)bm * BM * D_DIM;
    const float* rg = rmat + (size_t)bn * BN * D_DIM;

    float acc[8][8];
#pragma unroll
    for (int i = 0; i < 8; i++)
#pragma unroll
        for (int j = 0; j < 8; j++) acc[i][j] = 0.0f;

    for (int k0 = 0; k0 < D_DIM; k0 += BK) {
        // Load 128x32 tiles of E and R (float4 global, scalar smem stores).
#pragma unroll
        for (int f = t; f < (BM * BK) / 4; f += 256) {
            int row = f >> 3;           // 0..127
            int kk  = (f & 7) << 2;     // 0,4,...,28
            float4 v = *(const float4*)(eg + row * D_DIM + k0 + kk);
            Es[row][kk + 0] = v.x; Es[row][kk + 1] = v.y;
            Es[row][kk + 2] = v.z; Es[row][kk + 3] = v.w;
            float4 u = *(const float4*)(rg + row * D_DIM + k0 + kk);
            Rs[row][kk + 0] = u.x; Rs[row][kk + 1] = u.y;
            Rs[row][kk + 2] = u.z; Rs[row][kk + 3] = u.w;
        }
        __syncthreads();

#pragma unroll
        for (int d = 0; d < BK; d++) {
            float a[8], b[8];
#pragma unroll
            for (int i = 0; i < 8; i++) a[i] = Es[ty + 16 * i][d];
#pragma unroll
            for (int j = 0; j < 8; j++) b[j] = Rs[tx + 16 * j][d];
#pragma unroll
            for (int i = 0; i < 8; i++)
#pragma unroll
                for (int j = 0; j < 8; j++)
                    acc[i][j] = fmaf(a[i], b[j], acc[i][j]);
        }
        __syncthreads();
    }

    // Epilogue: pack sign bits. Thread owns rows m = ty+16i, cols n = tx+16j.
    // Bit position of col n in word n/32 is tx + 16*(j&1); one ballot covers
    // 16 cols for both rows (ty even = lanes 0..15, ty odd = lanes 16..31).
    const int lane     = t & 31;
    const int warp_ty0 = (t >> 5) << 1;          // even ty of this warp
    const unsigned mrow = bm * BM;

#pragma unroll
    for (int i = 0; i < 8; i++) {
        unsigned bal[8];
#pragma unroll
        for (int j = 0; j < 8; j++)
            bal[j] = __ballot_sync(0xffffffffu, acc[i][j] > 0.0f);
        if (lane < 8) {
            int w    = lane & 3;                 // word 0..3 of this 128-bit tile
            int rsel = lane >> 2;                // 0: even row, 1: odd row
            unsigned lo = bal[2 * w], hi = bal[2 * w + 1];
            unsigned word = rsel ? ((lo >> 16) | (hi & 0xffff0000u))
                                 : ((lo & 0xffffu) | (hi << 16));
            int m = warp_ty0 + rsel + 16 * i;
            codes[(size_t)(mrow + m) * (NBITS / 32) + bn * 4 + w] = word;
        }
    }
}

// ---------------------------------------------------------------------------
// Kernel 2: popcount Hamming -> cos -> masked output in [BAT,L,A,B] layout.
// One block per (l, b, 64-doc-chunk). 256 threads, 4x4 microtile.
// ---------------------------------------------------------------------------
__global__ __launch_bounds__(256)
void simmat_kernel(const int* __restrict__ qtok,
                   const int* __restrict__ dtok,
                   float* __restrict__ out)
{
    __shared__ unsigned qw[A_DIM][33];
    __shared__ unsigned dw[64][33];
    __shared__ int s1[A_DIM];
    __shared__ int s2[64];
    __shared__ int qm[A_DIM];
    __shared__ int dm[64];

    const int t  = threadIdx.x;
    const int cc = blockIdx.x;   // doc chunk 0..15
    const int b  = blockIdx.y;
    const int l  = blockIdx.z;

    const unsigned* qbase = g_codes_q + (size_t)(l * BAT + b) * A_DIM * 32;
    const unsigned* dbase = g_codes_d +
        ((size_t)(l * BAT + b) * B_DIM + (size_t)cc * 64) * 32;

#pragma unroll
    for (int f = t; f < 64 * 32; f += 256) {
        int row = f >> 5, w = f & 31;
        qw[row][w] = qbase[f];
        dw[row][w] = dbase[f];
    }
    if (t < 64)        qm[t]      = qtok[b * A_DIM + t];
    else if (t < 128)  dm[t - 64] = dtok[b * B_DIM + cc * 64 + (t - 64)];
    __syncthreads();

    if (t < 64) {
        int s = 0;
#pragma unroll
        for (int w = 0; w < 32; w++) s += __popc(qw[t][w]);
        s1[t] = s;
    } else if (t < 128) {
        int s = 0;
#pragma unroll
        for (int w = 0; w < 32; w++) s += __popc(dw[t - 64][w]);
        s2[t - 64] = s;
    }
    __syncthreads();

    const int ta = t >> 4;   // a-group lane
    const int tc = t & 15;   // c-group lane
    int dot[4][4];
#pragma unroll
    for (int ai = 0; ai < 4; ai++)
#pragma unroll
        for (int ci = 0; ci < 4; ci++) dot[ai][ci] = 0;

#pragma unroll
    for (int w = 0; w < 32; w++) {
        unsigned qa[4], dc[4];
#pragma unroll
        for (int ai = 0; ai < 4; ai++) qa[ai] = qw[ta + 16 * ai][w];
#pragma unroll
        for (int ci = 0; ci < 4; ci++) dc[ci] = dw[tc + 16 * ci][w];
#pragma unroll
        for (int ai = 0; ai < 4; ai++)
#pragma unroll
            for (int ci = 0; ci < 4; ci++)
                dot[ai][ci] += __popc(qa[ai] & dc[ci]);
    }

    const float kfac = 3.14159265358979323846f / (float)NBITS;
#pragma unroll
    for (int ai = 0; ai < 4; ai++) {
        int a = ta + 16 * ai;
        bool qz = (qm[a] == 0);
        int  sa = s1[a];
        size_t obase = ((((size_t)b * L_DIM + l) * A_DIM + a) * B_DIM)
                       + (size_t)cc * 64;
#pragma unroll
        for (int ci = 0; ci < 4; ci++) {
            int c   = tc + 16 * ci;
            int ham = sa + s2[c] - 2 * dot[ai][ci];
            float v = (qz || dm[c] == 0) ? 0.0f
                                         : __cosf(kfac * (float)ham);
            out[obase + c] = v;
        }
    }
}

// ---------------------------------------------------------------------------
extern "C" void kernel_launch(void* const* d_in, const int* in_sizes, int n_in,
                              void* d_out, int out_size)
{
    const float* qe = (const float*)d_in[0];   // query_embed
    const float* de = (const float*)d_in[1];   // doc_embed
    const int*   qt = (const int*)d_in[2];     // query_tok
    const int*   dt = (const int*)d_in[3];     // doc_tok
    const float* r  = (const float*)d_in[4];   // lsh projection
    float* out = (float*)d_out;

    unsigned *cq = nullptr, *cd = nullptr;
    cudaGetSymbolAddress((void**)&cq, g_codes_q);
    cudaGetSymbolAddress((void**)&cd, g_codes_d);

    // query codes: M = 2*32*64 = 4096 rows -> 32 m-tiles x 8 n-tiles
    codes_kernel<<<dim3(NBITS / BN, (L_DIM * BAT * A_DIM) / BM), 256>>>(qe, r, cq);
    // doc codes: M = 2*32*1024 = 65536 rows -> 512 m-tiles x 8 n-tiles
    codes_kernel<<<dim3(NBITS / BN, (L_DIM * BAT * B_DIM) / BM), 256>>>(de, r, cd);
    // simmat: one block per (l, b, 64-doc chunk)
    simmat_kernel<<<dim3(B_DIM / 64, BAT, L_DIM), 256>>>(qt, dt, out);
}

// round 7
// speedup vs baseline: 1.0906x; 1.0906x over previous
#include <cuda_runtime.h>
#include <cstdint>
#include <cstddef>

// Shapes (fixed by the problem)
#define L_DIM   2
#define BAT     32
#define A_DIM   64
#define B_DIM   1024
#define D_DIM   128
#define NBITS   1024

// Packed sign codes: 32 uint32 words per row (1024 bits)
__device__ unsigned g_codes_q[L_DIM * BAT * A_DIM * (NBITS / 32)];
__device__ unsigned g_codes_d[L_DIM * BAT * B_DIM * (NBITS / 32)];

// tf32 hi/lo split arrays, fragment-permuted: [row][ks(16)][t(4)][4 words]
//   word0 = hi(k=ks*8+t), word1 = hi(k+4), word2 = lo(k), word3 = lo(k+4)
__device__ uint32_t g_split_q[(size_t)4096 * 256];
__device__ uint32_t g_split_d[(size_t)65536 * 256];
__device__ uint32_t g_split_r[(size_t)1024 * 256];

// ---------------------------------------------------------------------------
__device__ __forceinline__ uint32_t smem_u32(const void* p) {
    uint32_t a;
    asm("{ .reg .u64 t; cvta.to.shared.u64 t, %1; cvt.u32.u64 %0, t; }"
        : "=r"(a) : "l"(p));
    return a;
}
__device__ __forceinline__ void cpa16(uint32_t saddr, const void* g) {
    asm volatile("cp.async.ca.shared.global [%0], [%1], 16;"
                 :: "r"(saddr), "l"(g) : "memory");
}
#define CP_COMMIT() asm volatile("cp.async.commit_group;" ::: "memory")
#define CP_WAIT1()  asm volatile("cp.async.wait_group 1;" ::: "memory")
#define CP_WAIT0()  asm volatile("cp.async.wait_group 0;" ::: "memory")

__device__ __forceinline__ void mma_tf32(float c[4],
                                         uint32_t a0, uint32_t a1, uint32_t a2, uint32_t a3,
                                         uint32_t b0, uint32_t b1) {
    asm volatile("mma.sync.aligned.m16n8k8.row.col.f32.tf32.tf32.f32 "
                 "{%0,%1,%2,%3}, {%4,%5,%6,%7}, {%8,%9}, {%0,%1,%2,%3};"
                 : "+f"(c[0]), "+f"(c[1]), "+f"(c[2]), "+f"(c[3])
                 : "r"(a0), "r"(a1), "r"(a2), "r"(a3), "r"(b0), "r"(b1));
}

// ---------------------------------------------------------------------------
// Pre-split: fp32 -> (tf32 hi, tf32 lo) in fragment-permuted layout.
// One thread per (row, kstep): reads 8 contiguous f32, writes 64B contiguous.
// ---------------------------------------------------------------------------
__global__ void split_kernel(const float* __restrict__ src,
                             uint32_t* __restrict__ dst, int total)
{
    int idx = blockIdx.x * blockDim.x + threadIdx.x;
    if (idx >= total) return;
    int row = idx >> 4, ks = idx & 15;
    const float4* p = (const float4*)(src + (size_t)row * D_DIM + ks * 8);
    float4 v0 = p[0], v1 = p[1];
    float f[8] = {v0.x, v0.y, v0.z, v0.w, v1.x, v1.y, v1.z, v1.w};
    uint32_t hi[8], lo[8];
#pragma unroll
    for (int j = 0; j < 8; j++) {
        asm("cvt.rna.tf32.f32 %0, %1;" : "=r"(hi[j]) : "f"(f[j]));
        float l = f[j] - __uint_as_float(hi[j]);
        asm("cvt.rna.tf32.f32 %0, %1;" : "=r"(lo[j]) : "f"(l));
    }
    uint4* o = (uint4*)(dst + (size_t)row * 256 + ks * 16);
#pragma unroll
    for (int t = 0; t < 4; t++)
        o[t] = make_uint4(hi[t], hi[t + 4], lo[t], lo[t + 4]);
}

// ---------------------------------------------------------------------------
// tf32 3-term split GEMM + sign-pack epilogue (legacy mma.sync path).
// CTA tile 128x128; B (R slice) resident in smem; A k32 chunks double-buffered.
// 8 warps, warp tile 64x32 (wm = wid>>2, wn = wid&3).
// ---------------------------------------------------------------------------
#define BROWB 1088                 // B smem row stride (bank-conflict free)
#define AROWB 320                  // A smem row stride
#define ABUFB (128 * AROWB)        // 40960 per A buffer
#define SM_A  (128 * BROWB)        // 139264 (B region size)
#define SMEMSZ (SM_A + 2 * ABUFB)  // 221184

__global__ __launch_bounds__(256, 1)
void lsh_mma_kernel(const uint32_t* __restrict__ Asp,
                    const uint32_t* __restrict__ Bsp,
                    unsigned* __restrict__ codes, int m_tiles)
{
    extern __shared__ char smem[];
    const uint32_t sb = smem_u32(smem);
    const int t    = threadIdx.x;
    const int wid  = t >> 5, lane = t & 31;
    const int g    = lane >> 2, tq = lane & 3;
    const int wm   = wid >> 2, wn = wid & 3;
    const int n_tile = blockIdx.x;

    // ---- B resident copy (group 0): 128 rows x 1KB ----
    {
        const uint32_t* bg = Bsp + (size_t)n_tile * 128 * 256;
#pragma unroll
        for (int i = 0; i < 32; i++) {
            int gi = t + 256 * i, row = gi >> 6, w = gi & 63;
            cpa16(sb + row * BROWB + w * 16, bg + (size_t)row * 256 + w * 4);
        }
        CP_COMMIT();
    }

    auto issueA = [&](int mt, int c, int buf) {
        const uint32_t* ag = Asp + (size_t)mt * 128 * 256 + c * 64;
#pragma unroll
        for (int i = 0; i < 8; i++) {
            int gi = t + 256 * i, row = gi >> 4, w = gi & 15;
            cpa16(sb + SM_A + buf * ABUFB + row * AROWB + w * 16,
                  ag + (size_t)row * 256 + w * 4);
        }
        CP_COMMIT();
    };

    int mt = blockIdx.y;
    if (mt < m_tiles) issueA(mt, 0, 0);

    for (; mt < m_tiles; mt += gridDim.y) {
        float C[4][4][4];
#pragma unroll
        for (int i = 0; i < 4; i++)
#pragma unroll
            for (int j = 0; j < 4; j++)
#pragma unroll
                for (int k = 0; k < 4; k++) C[i][j][k] = 0.0f;

        const int next_mt = mt + gridDim.y;

        for (int c = 0; c < 4; c++) {
            const int buf = c & 1;
            bool more;
            if (c < 3)                  { issueA(mt, c + 1, (c + 1) & 1); more = true; }
            else if (next_mt < m_tiles) { issueA(next_mt, 0, 0);          more = true; }
            else                          more = false;
            if (more) CP_WAIT1(); else CP_WAIT0();
            __syncthreads();

#pragma unroll
            for (int ksc = 0; ksc < 4; ksc++) {
                const int ks = c * 4 + ksc;
                uint4 B4[4], A4[4][2];
#pragma unroll
                for (int nf = 0; nf < 4; nf++) {
                    int n = wn * 32 + nf * 8 + g;
                    B4[nf] = *(const uint4*)(smem + n * BROWB + ks * 64 + tq * 16);
                }
#pragma unroll
                for (int mf = 0; mf < 4; mf++) {
                    int r0 = wm * 64 + mf * 16 + g;
                    const char* base = smem + SM_A + buf * ABUFB + ksc * 64 + tq * 16;
                    A4[mf][0] = *(const uint4*)(base + r0 * AROWB);
                    A4[mf][1] = *(const uint4*)(base + (r0 + 8) * AROWB);
                }
                // term hh: ah x bh  (16 independent accumulator chains)
#pragma unroll
                for (int mf = 0; mf < 4; mf++)
#pragma unroll
                    for (int nf = 0; nf < 4; nf++)
                        mma_tf32(C[mf][nf],
                                 A4[mf][0].x, A4[mf][1].x, A4[mf][0].y, A4[mf][1].y,
                                 B4[nf].x, B4[nf].y);
                // term hl: ah x bl
#pragma unroll
                for (int mf = 0; mf < 4; mf++)
#pragma unroll
                    for (int nf = 0; nf < 4; nf++)
                        mma_tf32(C[mf][nf],
                                 A4[mf][0].x, A4[mf][1].x, A4[mf][0].y, A4[mf][1].y,
                                 B4[nf].z, B4[nf].w);
                // term lh: al x bh
#pragma unroll
                for (int mf = 0; mf < 4; mf++)
#pragma unroll
                    for (int nf = 0; nf < 4; nf++)
                        mma_tf32(C[mf][nf],
                                 A4[mf][0].z, A4[mf][1].z, A4[mf][0].w, A4[mf][1].w,
                                 B4[nf].x, B4[nf].y);
            }
            __syncthreads();
        }

        // ---- epilogue: sign-pack via shfl-OR over the 4 t-lanes ----
#pragma unroll
        for (int mf = 0; mf < 4; mf++) {
            unsigned m0 = 0, m1 = 0;
#pragma unroll
            for (int nf = 0; nf < 4; nf++) {
                int p = nf * 8 + tq * 2;
                m0 |= (C[mf][nf][0] > 0.0f ? 1u : 0u) << p;
                m0 |= (C[mf][nf][1] > 0.0f ? 1u : 0u) << (p + 1);
                m1 |= (C[mf][nf][2] > 0.0f ? 1u : 0u) << p;
                m1 |= (C[mf][nf][3] > 0.0f ? 1u : 0u) << (p + 1);
            }
            m0 |= __shfl_xor_sync(0xffffffffu, m0, 1);
            m0 |= __shfl_xor_sync(0xffffffffu, m0, 2);
            m1 |= __shfl_xor_sync(0xffffffffu, m1, 1);
            m1 |= __shfl_xor_sync(0xffffffffu, m1, 2);
            if (tq == 0) {
                size_t r0 = (size_t)mt * 128 + wm * 64 + mf * 16 + g;
                int wcol = n_tile * 4 + wn;
                codes[r0 * 32 + wcol]       = m0;
                codes[(r0 + 8) * 32 + wcol] = m1;
            }
        }
    }
}

// ---------------------------------------------------------------------------
// popcount Hamming -> cos -> masked output in [BAT,L,A,B] layout. (unchanged)
// ---------------------------------------------------------------------------
__global__ __launch_bounds__(256)
void simmat_kernel(const int* __restrict__ qtok,
                   const int* __restrict__ dtok,
                   float* __restrict__ out)
{
    __shared__ unsigned qw[A_DIM][33];
    __shared__ unsigned dw[64][33];
    __shared__ int s1[A_DIM];
    __shared__ int s2[64];
    __shared__ int qm[A_DIM];
    __shared__ int dm[64];

    const int t  = threadIdx.x;
    const int cc = blockIdx.x;
    const int b  = blockIdx.y;
    const int l  = blockIdx.z;

    const unsigned* qbase = g_codes_q + (size_t)(l * BAT + b) * A_DIM * 32;
    const unsigned* dbase = g_codes_d +
        ((size_t)(l * BAT + b) * B_DIM + (size_t)cc * 64) * 32;

#pragma unroll
    for (int f = t; f < 64 * 32; f += 256) {
        int row = f >> 5, w = f & 31;
        qw[row][w] = qbase[f];
        dw[row][w] = dbase[f];
    }
    if (t < 64)        qm[t]      = qtok[b * A_DIM + t];
    else if (t < 128)  dm[t - 64] = dtok[b * B_DIM + cc * 64 + (t - 64)];
    __syncthreads();

    if (t < 64) {
        int s = 0;
#pragma unroll
        for (int w = 0; w < 32; w++) s += __popc(qw[t][w]);
        s1[t] = s;
    } else if (t < 128) {
        int s = 0;
#pragma unroll
        for (int w = 0; w < 32; w++) s += __popc(dw[t - 64][w]);
        s2[t - 64] = s;
    }
    __syncthreads();

    const int ta = t >> 4;
    const int tc = t & 15;
    int dot[4][4];
#pragma unroll
    for (int ai = 0; ai < 4; ai++)
#pragma unroll
        for (int ci = 0; ci < 4; ci++) dot[ai][ci] = 0;

#pragma unroll
    for (int w = 0; w < 32; w++) {
        unsigned qa[4], dc[4];
#pragma unroll
        for (int ai = 0; ai < 4; ai++) qa[ai] = qw[ta + 16 * ai][w];
#pragma unroll
        for (int ci = 0; ci < 4; ci++) dc[ci] = dw[tc + 16 * ci][w];
#pragma unroll
        for (int ai = 0; ai < 4; ai++)
#pragma unroll
            for (int ci = 0; ci < 4; ci++)
                dot[ai][ci] += __popc(qa[ai] & dc[ci]);
    }

    const float kfac = 3.14159265358979323846f / (float)NBITS;
#pragma unroll
    for (int ai = 0; ai < 4; ai++) {
        int a = ta + 16 * ai;
        bool qz = (qm[a] == 0);
        int  sa = s1[a];
        size_t obase = ((((size_t)b * L_DIM + l) * A_DIM + a) * B_DIM)
                       + (size_t)cc * 64;
#pragma unroll
        for (int ci = 0; ci < 4; ci++) {
            int c   = tc + 16 * ci;
            int ham = sa + s2[c] - 2 * dot[ai][ci];
            float v = (qz || dm[c] == 0) ? 0.0f
                                         : __cosf(kfac * (float)ham);
            out[obase + c] = v;
        }
    }
}

// ---------------------------------------------------------------------------
extern "C" void kernel_launch(void* const* d_in, const int* in_sizes, int n_in,
                              void* d_out, int out_size)
{
    const float* qe = (const float*)d_in[0];
    const float* de = (const float*)d_in[1];
    const int*   qt = (const int*)d_in[2];
    const int*   dt = (const int*)d_in[3];
    const float* r  = (const float*)d_in[4];
    float* out = (float*)d_out;

    unsigned *cq = nullptr, *cd = nullptr;
    uint32_t *sq = nullptr, *sd = nullptr, *sr = nullptr;
    cudaGetSymbolAddress((void**)&cq, g_codes_q);
    cudaGetSymbolAddress((void**)&cd, g_codes_d);
    cudaGetSymbolAddress((void**)&sq, g_split_q);
    cudaGetSymbolAddress((void**)&sd, g_split_d);
    cudaGetSymbolAddress((void**)&sr, g_split_r);

    // Pre-split fp32 -> tf32 hi/lo (fragment-permuted layout)
    split_kernel<<<(4096 * 16 + 255) / 256, 256>>>(qe, sq, 4096 * 16);
    split_kernel<<<(65536 * 16 + 255) / 256, 256>>>(de, sd, 65536 * 16);
    split_kernel<<<(1024 * 16 + 255) / 256, 256>>>(r, sr, 1024 * 16);

    cudaFuncSetAttribute(lsh_mma_kernel,
                         cudaFuncAttributeMaxDynamicSharedMemorySize, SMEMSZ);

    // query: 32 m-tiles; doc: 512 m-tiles. 8 n-slices x 18 persistent rows.
    lsh_mma_kernel<<<dim3(8, 18), 256, SMEMSZ>>>(sq, sr, cq, 32);
    lsh_mma_kernel<<<dim3(8, 18), 256, SMEMSZ>>>(sd, sr, cd, 512);

    simmat_kernel<<<dim3(B_DIM / 64, BAT, L_DIM), 256>>>(qt, dt, out);
}